// round 1
// baseline (speedup 1.0000x reference)
#include <cuda_runtime.h>
#include <cuda_bf16.h>

#define N_NODES 50000
#define N_EDGES 800000
#define F_DIM   512      // IN and HIDDEN width
#define F_OUT   256

// ---------------- persistent device scratch (no allocs allowed) ----------------
__device__ float g_H[(size_t)N_NODES * F_DIM];   // GEMM output (pre-aggregation)
__device__ float g_X[(size_t)N_NODES * F_DIM];   // layer activation (post-aggregation)
__device__ int   g_cnt_out[N_NODES];
__device__ int   g_cnt_in[N_NODES];
__device__ float g_out_norm[N_NODES];
__device__ float g_in_norm[N_NODES];
__device__ int   g_row_ptr[N_NODES + 1];
__device__ int   g_cursor[N_NODES];
__device__ int   g_esrc[N_EDGES];
__device__ int   g_is64;

// ---------------- index dtype sniffing (int32 vs int64 source data) ------------
__global__ void detect_kernel(const int* p) {
    // if indices are int64 (values < 50000), every odd 32-bit word is 0.
    int all0 = 1;
    for (int i = 1; i < 256; i += 2)
        if (p[i] != 0) { all0 = 0; break; }
    g_is64 = all0;
}

__device__ __forceinline__ int load_idx(const void* p, int i) {
    if (g_is64) return (int)((const long long*)p)[i];
    return ((const int*)p)[i];
}

// ---------------- graph preprocessing ----------------
__global__ void zero_counts_kernel() {
    int i = blockIdx.x * blockDim.x + threadIdx.x;
    if (i < N_NODES) { g_cnt_out[i] = 0; g_cnt_in[i] = 0; }
}

__global__ void degree_kernel(const void* src, const void* dst) {
    int stride = gridDim.x * blockDim.x;
    for (int e = blockIdx.x * blockDim.x + threadIdx.x; e < N_EDGES; e += stride) {
        atomicAdd(&g_cnt_out[load_idx(src, e)], 1);
        atomicAdd(&g_cnt_in[load_idx(dst, e)], 1);
    }
}

__global__ void norm_kernel() {
    int i = blockIdx.x * blockDim.x + threadIdx.x;
    if (i < N_NODES) {
        int co = g_cnt_out[i]; if (co < 1) co = 1;
        int ci = g_cnt_in[i];  if (ci < 1) ci = 1;
        g_out_norm[i] = rsqrtf((float)co);
        g_in_norm[i]  = rsqrtf((float)ci);
    }
}

// single-block exclusive scan over g_cnt_in -> g_row_ptr (+ copy to g_cursor)
__global__ void scan_kernel() {
    __shared__ int sh[1024];
    __shared__ int carry;
    int tid = threadIdx.x;
    if (tid == 0) carry = 0;
    __syncthreads();
    for (int base = 0; base < N_NODES; base += 1024) {
        int i = base + tid;
        int v = (i < N_NODES) ? g_cnt_in[i] : 0;
        sh[tid] = v;
        __syncthreads();
        int mycarry = carry;
        for (int off = 1; off < 1024; off <<= 1) {
            int t = (tid >= off) ? sh[tid - off] : 0;
            __syncthreads();
            sh[tid] += t;
            __syncthreads();
        }
        int excl = mycarry + sh[tid] - v;
        if (i < N_NODES) { g_row_ptr[i] = excl; g_cursor[i] = excl; }
        int total = sh[1023];
        __syncthreads();
        if (tid == 0) carry = mycarry + total;
        __syncthreads();
    }
    if (tid == 0) g_row_ptr[N_NODES] = carry;   // = N_EDGES
}

__global__ void fill_kernel(const void* src, const void* dst) {
    int stride = gridDim.x * blockDim.x;
    for (int e = blockIdx.x * blockDim.x + threadIdx.x; e < N_EDGES; e += stride) {
        int d = load_idx(dst, e);
        int pos = atomicAdd(&g_cursor[d], 1);
        g_esrc[pos] = load_idx(src, e);
    }
}

// ---------------- SGEMM: H[m,n] = (sum_k X[m,k]*W[k,n]) * out_norm[m] ----------
// BM=64, BN=64, BK=16, 256 threads, 4x4 micro-tile. K fixed = 512.
__global__ __launch_bounds__(256)
void gemm_scale_kernel(const float* __restrict__ X,
                       const float* __restrict__ W,
                       float* __restrict__ H,
                       int M, int N) {
    __shared__ float As[16][65];   // [k][m], padded
    __shared__ float Bs[16][64];   // [k][n]

    int tid = threadIdx.x;
    int tx = tid & 15;         // 0..15 -> n micro
    int ty = tid >> 4;         // 0..15 -> m micro
    int m0 = blockIdx.y * 64;
    int n0 = blockIdx.x * 64;

    int a_row = tid >> 2;            // 0..63
    int a_k   = (tid & 3) << 2;      // 0,4,8,12
    int b_k   = tid >> 4;            // 0..15
    int b_n   = (tid & 15) << 2;     // 0..60

    float acc[4][4] = {};

    for (int k0 = 0; k0 < 512; k0 += 16) {
        float4 av = make_float4(0.f, 0.f, 0.f, 0.f);
        int grow = m0 + a_row;
        if (grow < M)
            av = *reinterpret_cast<const float4*>(&X[(size_t)grow * 512 + k0 + a_k]);
        As[a_k + 0][a_row] = av.x;
        As[a_k + 1][a_row] = av.y;
        As[a_k + 2][a_row] = av.z;
        As[a_k + 3][a_row] = av.w;

        float4 bv = *reinterpret_cast<const float4*>(&W[(size_t)(k0 + b_k) * N + n0 + b_n]);
        *reinterpret_cast<float4*>(&Bs[b_k][b_n]) = bv;
        __syncthreads();

        #pragma unroll
        for (int kk = 0; kk < 16; kk++) {
            float ra[4];
            #pragma unroll
            for (int i = 0; i < 4; i++) ra[i] = As[kk][ty * 4 + i];
            float4 rbv = *reinterpret_cast<const float4*>(&Bs[kk][tx * 4]);
            float rb[4] = {rbv.x, rbv.y, rbv.z, rbv.w};
            #pragma unroll
            for (int i = 0; i < 4; i++)
                #pragma unroll
                for (int j = 0; j < 4; j++)
                    acc[i][j] += ra[i] * rb[j];
        }
        __syncthreads();
    }

    #pragma unroll
    for (int i = 0; i < 4; i++) {
        int row = m0 + ty * 4 + i;
        if (row < M) {
            float s = g_out_norm[row];
            float4 v;
            v.x = acc[i][0] * s;
            v.y = acc[i][1] * s;
            v.z = acc[i][2] * s;
            v.w = acc[i][3] * s;
            *reinterpret_cast<float4*>(&H[(size_t)row * N + n0 + tx * 4]) = v;
        }
    }
}

// ---------------- CSR gather-aggregate + in_norm + bias (+ReLU) ----------------
template <int WIDTH, bool RELU>
__global__ void aggregate_kernel(const float* __restrict__ H,
                                 const float* __restrict__ bias,
                                 float* __restrict__ out) {
    int n = blockIdx.x;
    int c = threadIdx.x * 4;          // blockDim = WIDTH/4
    float4 acc = make_float4(0.f, 0.f, 0.f, 0.f);
    int e0 = g_row_ptr[n];
    int e1 = g_row_ptr[n + 1];
    for (int e = e0; e < e1; e++) {
        int s = g_esrc[e];
        float4 v = *reinterpret_cast<const float4*>(&H[(size_t)s * WIDTH + c]);
        acc.x += v.x; acc.y += v.y; acc.z += v.z; acc.w += v.w;
    }
    float inn = g_in_norm[n];
    float4 b = *reinterpret_cast<const float4*>(&bias[c]);
    float4 r;
    r.x = acc.x * inn + b.x;
    r.y = acc.y * inn + b.y;
    r.z = acc.z * inn + b.z;
    r.w = acc.w * inn + b.w;
    if (RELU) {
        r.x = fmaxf(r.x, 0.f); r.y = fmaxf(r.y, 0.f);
        r.z = fmaxf(r.z, 0.f); r.w = fmaxf(r.w, 0.f);
    }
    *reinterpret_cast<float4*>(&out[(size_t)n * WIDTH + c]) = r;
}

// ---------------- launch ----------------
extern "C" void kernel_launch(void* const* d_in, const int* in_sizes, int n_in,
                              void* d_out, int out_size) {
    const float* feat = (const float*)d_in[0];
    const void*  src  = d_in[1];
    const void*  dst  = d_in[2];
    const float* W0   = (const float*)d_in[3];
    const float* b0   = (const float*)d_in[4];
    const float* W1   = (const float*)d_in[5];
    const float* b1   = (const float*)d_in[6];
    const float* W2   = (const float*)d_in[7];
    const float* b2   = (const float*)d_in[8];
    float* out = (float*)d_out;

    float *pH = nullptr, *pX = nullptr;
    cudaGetSymbolAddress((void**)&pH, g_H);
    cudaGetSymbolAddress((void**)&pX, g_X);

    // graph preprocessing
    detect_kernel<<<1, 1>>>((const int*)src);
    zero_counts_kernel<<<(N_NODES + 255) / 256, 256>>>();
    degree_kernel<<<512, 256>>>(src, dst);
    norm_kernel<<<(N_NODES + 255) / 256, 256>>>();
    scan_kernel<<<1, 1024>>>();
    fill_kernel<<<512, 256>>>(src, dst);

    dim3 g512(512 / 64, (N_NODES + 63) / 64);
    dim3 g256(256 / 64, (N_NODES + 63) / 64);

    // layer 0: feat(512) -> hidden(512), ReLU
    gemm_scale_kernel<<<g512, 256>>>(feat, W0, pH, N_NODES, 512);
    aggregate_kernel<512, true><<<N_NODES, 128>>>(pH, b0, pX);

    // layer 1: hidden(512) -> hidden(512), ReLU
    gemm_scale_kernel<<<g512, 256>>>(pX, W1, pH, N_NODES, 512);
    aggregate_kernel<512, true><<<N_NODES, 128>>>(pH, b1, pX);

    // layer 2: hidden(512) -> out(256), no activation
    gemm_scale_kernel<<<g256, 256>>>(pX, W2, pH, N_NODES, 256);
    aggregate_kernel<256, false><<<N_NODES, 64>>>(pH, b2, out);
}

// round 3
// speedup vs baseline: 2.4523x; 2.4523x over previous
#include <cuda_runtime.h>
#include <cuda_bf16.h>
#include <cstdint>

#define N_NODES 50000
#define N_EDGES 800000
#define F_DIM   512
#define F_OUT   256

// ---------------- persistent device scratch (no allocs allowed) ----------------
__device__ float g_H[(size_t)N_NODES * F_DIM];   // GEMM output (pre-aggregation)
__device__ float g_X[(size_t)N_NODES * F_DIM];   // layer activation (post-aggregation)
__device__ float g_Wt[512 * 512];                // transposed weights: Wt[n][k]
__device__ int   g_cnt_out[N_NODES];
__device__ int   g_cnt_in[N_NODES];
__device__ float g_out_norm[N_NODES];
__device__ float g_in_norm[N_NODES];
__device__ int   g_row_ptr[N_NODES + 1];
__device__ int   g_cursor[N_NODES];
__device__ int   g_esrc[N_EDGES];
__device__ int   g_is64;

// ============================ index dtype sniffing ============================
__global__ void detect_kernel(const int* p) {
    int all0 = 1;
    for (int i = 1; i < 256; i += 2)
        if (p[i] != 0) { all0 = 0; break; }
    g_is64 = all0;
}
__device__ __forceinline__ int load_idx(const void* p, int i) {
    if (g_is64) return (int)((const long long*)p)[i];
    return ((const int*)p)[i];
}

// ============================ graph preprocessing ============================
__global__ void zero_counts_kernel() {
    int i = blockIdx.x * blockDim.x + threadIdx.x;
    if (i < N_NODES) { g_cnt_out[i] = 0; g_cnt_in[i] = 0; }
}
__global__ void degree_kernel(const void* src, const void* dst) {
    int stride = gridDim.x * blockDim.x;
    for (int e = blockIdx.x * blockDim.x + threadIdx.x; e < N_EDGES; e += stride) {
        atomicAdd(&g_cnt_out[load_idx(src, e)], 1);
        atomicAdd(&g_cnt_in[load_idx(dst, e)], 1);
    }
}
__global__ void norm_kernel() {
    int i = blockIdx.x * blockDim.x + threadIdx.x;
    if (i < N_NODES) {
        int co = g_cnt_out[i]; if (co < 1) co = 1;
        int ci = g_cnt_in[i];  if (ci < 1) ci = 1;
        g_out_norm[i] = rsqrtf((float)co);
        g_in_norm[i]  = rsqrtf((float)ci);
    }
}
__global__ void scan_kernel() {
    __shared__ int sh[1024];
    __shared__ int carry;
    int tid = threadIdx.x;
    if (tid == 0) carry = 0;
    __syncthreads();
    for (int base = 0; base < N_NODES; base += 1024) {
        int i = base + tid;
        int v = (i < N_NODES) ? g_cnt_in[i] : 0;
        sh[tid] = v;
        __syncthreads();
        int mycarry = carry;
        for (int off = 1; off < 1024; off <<= 1) {
            int t = (tid >= off) ? sh[tid - off] : 0;
            __syncthreads();
            sh[tid] += t;
            __syncthreads();
        }
        int excl = mycarry + sh[tid] - v;
        if (i < N_NODES) { g_row_ptr[i] = excl; g_cursor[i] = excl; }
        int total = sh[1023];
        __syncthreads();
        if (tid == 0) carry = mycarry + total;
        __syncthreads();
    }
    if (tid == 0) g_row_ptr[N_NODES] = carry;
}
__global__ void fill_kernel(const void* src, const void* dst) {
    int stride = gridDim.x * blockDim.x;
    for (int e = blockIdx.x * blockDim.x + threadIdx.x; e < N_EDGES; e += stride) {
        int d = load_idx(dst, e);
        int pos = atomicAdd(&g_cursor[d], 1);
        g_esrc[pos] = load_idx(src, e);
    }
}

// ============================ weight transpose ============================
// Wt[n*512 + k] = W[k*N + n]   (K always 512; N = 512 or 256)
__global__ void transpose_kernel(const float* __restrict__ W, float* __restrict__ Wt, int N) {
    __shared__ float tile[32][33];
    int n = blockIdx.x * 32 + threadIdx.x;
    int k = blockIdx.y * 32 + threadIdx.y;
    #pragma unroll
    for (int dy = 0; dy < 32; dy += 8)
        tile[threadIdx.y + dy][threadIdx.x] = W[(size_t)(k + dy) * N + n];
    __syncthreads();
    int n2 = blockIdx.x * 32 + threadIdx.y;
    int k2 = blockIdx.y * 32 + threadIdx.x;
    #pragma unroll
    for (int dy = 0; dy < 32; dy += 8)
        Wt[(size_t)(n2 + dy) * 512 + k2] = tile[threadIdx.x][threadIdx.y + dy];
}

// ============================ tf32 mma.sync GEMM ============================
// H[m, n] = (sum_k X[m,k] * Wt[n,k]) * out_norm[m]
// BM=128, BN=128, BK=32, 256 thr (8 warps), warp tile 64x32, double-buffer cp.async.
#define BK        32
#define ROW_STR   36                         // floats per smem row (bank-conflict-free)
#define A_FLOATS  (128 * ROW_STR)            // 4608
#define STAGE_FLOATS (2 * A_FLOATS)          // A then B
#define SMEM_GEMM (2 * STAGE_FLOATS * 4)     // 73728 B

__device__ __forceinline__ uint32_t smem_u32(const void* p) {
    uint32_t a;
    asm("{ .reg .u64 t; cvta.to.shared.u64 t, %1; cvt.u32.u64 %0, t; }" : "=r"(a) : "l"(p));
    return a;
}
__device__ __forceinline__ void cp_async16(uint32_t dst, const void* src) {
    asm volatile("cp.async.ca.shared.global [%0], [%1], 16;" :: "r"(dst), "l"(src));
}
__device__ __forceinline__ uint32_t f2tf32(float x) {
    uint32_t r;
    asm("cvt.rna.tf32.f32 %0, %1;" : "=r"(r) : "f"(x));
    return r;
}
__device__ __forceinline__ void mma_tf32(float c[4],
                                         uint32_t a0, uint32_t a1, uint32_t a2, uint32_t a3,
                                         uint32_t b0, uint32_t b1) {
    asm volatile("mma.sync.aligned.m16n8k8.row.col.f32.tf32.tf32.f32 "
        "{%0,%1,%2,%3}, {%4,%5,%6,%7}, {%8,%9}, {%0,%1,%2,%3};"
        : "+f"(c[0]), "+f"(c[1]), "+f"(c[2]), "+f"(c[3])
        : "r"(a0), "r"(a1), "r"(a2), "r"(a3), "r"(b0), "r"(b1));
}

__global__ __launch_bounds__(256)
void gemm_tf32_mma(const float* __restrict__ X, const float* __restrict__ Wt,
                   float* __restrict__ H, int M, int N) {
    extern __shared__ float smem[];
    int tid  = threadIdx.x;
    int wid  = tid >> 5;
    int lane = tid & 31;
    int m0 = blockIdx.y * 128;
    int n0 = blockIdx.x * 128;

    int wm = wid & 1;        // 0..1 -> warp m offset (64 rows each)
    int wn = wid >> 1;       // 0..3 -> warp n offset (32 cols each)
    int qrow = lane >> 2;    // 0..7
    int qk   = lane & 3;     // 0..3

    // copy indices: thread t covers rows (t/8)+32*pass, float4 col t%8
    int cr = tid >> 3;       // 0..31
    int cc = tid & 7;        // 0..7  (float4 index within 32 floats)

    float acc[4][4][4];
    #pragma unroll
    for (int i = 0; i < 4; i++)
        #pragma unroll
        for (int j = 0; j < 4; j++)
            #pragma unroll
            for (int q = 0; q < 4; q++) acc[i][j][q] = 0.f;

    const int n_chunks = 512 / BK;   // 16

    // ---- prefetch chunk 0 into stage 0 ----
    {
        float* As = smem;
        float* Bs = smem + A_FLOATS;
        #pragma unroll
        for (int pass = 0; pass < 4; pass++) {
            int r = cr + pass * 32;
            uint32_t adst = smem_u32(&As[r * ROW_STR + cc * 4]);
            int grow = m0 + r;
            if (grow < M) cp_async16(adst, &X[(size_t)grow * 512 + cc * 4]);
            else *reinterpret_cast<float4*>(&As[r * ROW_STR + cc * 4]) = make_float4(0,0,0,0);
            uint32_t bdst = smem_u32(&Bs[r * ROW_STR + cc * 4]);
            cp_async16(bdst, &Wt[(size_t)(n0 + r) * 512 + cc * 4]);
        }
        asm volatile("cp.async.commit_group;");
    }

    for (int i = 0; i < n_chunks; i++) {
        // prefetch chunk i+1 into the other stage
        if (i + 1 < n_chunks) {
            int k0 = (i + 1) * BK;
            float* As = smem + ((i + 1) & 1) * STAGE_FLOATS;
            float* Bs = As + A_FLOATS;
            #pragma unroll
            for (int pass = 0; pass < 4; pass++) {
                int r = cr + pass * 32;
                uint32_t adst = smem_u32(&As[r * ROW_STR + cc * 4]);
                int grow = m0 + r;
                if (grow < M) cp_async16(adst, &X[(size_t)grow * 512 + k0 + cc * 4]);
                else *reinterpret_cast<float4*>(&As[r * ROW_STR + cc * 4]) = make_float4(0,0,0,0);
                uint32_t bdst = smem_u32(&Bs[r * ROW_STR + cc * 4]);
                cp_async16(bdst, &Wt[(size_t)(n0 + r) * 512 + k0 + cc * 4]);
            }
            asm volatile("cp.async.commit_group;");
            asm volatile("cp.async.wait_group 1;");
        } else {
            asm volatile("cp.async.wait_group 0;");
        }
        __syncthreads();

        const float* As = smem + (i & 1) * STAGE_FLOATS;
        const float* Bs = As + A_FLOATS;

        #pragma unroll
        for (int kb = 0; kb < BK; kb += 8) {
            uint32_t af[4][4];
            #pragma unroll
            for (int mf = 0; mf < 4; mf++) {
                const float* ap = &As[(wm * 64 + mf * 16 + qrow) * ROW_STR + kb + qk];
                af[mf][0] = f2tf32(ap[0]);
                af[mf][1] = f2tf32(ap[8 * ROW_STR]);
                af[mf][2] = f2tf32(ap[4]);
                af[mf][3] = f2tf32(ap[8 * ROW_STR + 4]);
            }
            uint32_t bf[4][2];
            #pragma unroll
            for (int nf = 0; nf < 4; nf++) {
                const float* bp = &Bs[(wn * 32 + nf * 8 + qrow) * ROW_STR + kb + qk];
                bf[nf][0] = f2tf32(bp[0]);
                bf[nf][1] = f2tf32(bp[4]);
            }
            #pragma unroll
            for (int mf = 0; mf < 4; mf++)
                #pragma unroll
                for (int nf = 0; nf < 4; nf++)
                    mma_tf32(acc[mf][nf], af[mf][0], af[mf][1], af[mf][2], af[mf][3],
                             bf[nf][0], bf[nf][1]);
        }
        __syncthreads();
    }

    // ---- epilogue: scale by out_norm, store ----
    #pragma unroll
    for (int mf = 0; mf < 4; mf++) {
        int row  = m0 + wm * 64 + mf * 16 + qrow;
        int row8 = row + 8;
        float s0 = (row  < M) ? g_out_norm[row]  : 0.f;
        float s1 = (row8 < M) ? g_out_norm[row8] : 0.f;
        #pragma unroll
        for (int nf = 0; nf < 4; nf++) {
            int col = n0 + wn * 32 + nf * 8 + qk * 2;
            if (row < M) {
                float2 v = make_float2(acc[mf][nf][0] * s0, acc[mf][nf][1] * s0);
                *reinterpret_cast<float2*>(&H[(size_t)row * N + col]) = v;
            }
            if (row8 < M) {
                float2 v = make_float2(acc[mf][nf][2] * s1, acc[mf][nf][3] * s1);
                *reinterpret_cast<float2*>(&H[(size_t)row8 * N + col]) = v;
            }
        }
    }
}

// ============================ CSR gather-aggregate ============================
template <int WIDTH, bool RELU>
__global__ void aggregate_kernel(const float* __restrict__ H,
                                 const float* __restrict__ bias,
                                 float* __restrict__ out) {
    int n = blockIdx.x;
    int c = threadIdx.x * 4;
    float4 acc = make_float4(0.f, 0.f, 0.f, 0.f);
    int e0 = g_row_ptr[n];
    int e1 = g_row_ptr[n + 1];
    for (int e = e0; e < e1; e++) {
        int s = g_esrc[e];
        float4 v = *reinterpret_cast<const float4*>(&H[(size_t)s * WIDTH + c]);
        acc.x += v.x; acc.y += v.y; acc.z += v.z; acc.w += v.w;
    }
    float inn = g_in_norm[n];
    float4 b = *reinterpret_cast<const float4*>(&bias[c]);
    float4 r;
    r.x = acc.x * inn + b.x;
    r.y = acc.y * inn + b.y;
    r.z = acc.z * inn + b.z;
    r.w = acc.w * inn + b.w;
    if (RELU) {
        r.x = fmaxf(r.x, 0.f); r.y = fmaxf(r.y, 0.f);
        r.z = fmaxf(r.z, 0.f); r.w = fmaxf(r.w, 0.f);
    }
    *reinterpret_cast<float4*>(&out[(size_t)n * WIDTH + c]) = r;
}

// ============================ launch ============================
extern "C" void kernel_launch(void* const* d_in, const int* in_sizes, int n_in,
                              void* d_out, int out_size) {
    const float* feat = (const float*)d_in[0];
    const void*  src  = d_in[1];
    const void*  dst  = d_in[2];
    const float* W0   = (const float*)d_in[3];
    const float* b0   = (const float*)d_in[4];
    const float* W1   = (const float*)d_in[5];
    const float* b1   = (const float*)d_in[6];
    const float* W2   = (const float*)d_in[7];
    const float* b2   = (const float*)d_in[8];
    float* out = (float*)d_out;

    float *pH = nullptr, *pX = nullptr, *pWt = nullptr;
    cudaGetSymbolAddress((void**)&pH, g_H);
    cudaGetSymbolAddress((void**)&pX, g_X);
    cudaGetSymbolAddress((void**)&pWt, g_Wt);

    cudaFuncSetAttribute(gemm_tf32_mma, cudaFuncAttributeMaxDynamicSharedMemorySize, SMEM_GEMM);

    // graph preprocessing
    detect_kernel<<<1, 1>>>((const int*)src);
    zero_counts_kernel<<<(N_NODES + 255) / 256, 256>>>();
    degree_kernel<<<512, 256>>>(src, dst);
    norm_kernel<<<(N_NODES + 255) / 256, 256>>>();
    scan_kernel<<<1, 1024>>>();
    fill_kernel<<<512, 256>>>(src, dst);

    int mtiles = (N_NODES + 127) / 128;   // 391

    // layer 0: feat(512) -> hidden(512), ReLU
    transpose_kernel<<<dim3(512 / 32, 512 / 32), dim3(32, 8)>>>(W0, pWt, 512);
    gemm_tf32_mma<<<dim3(4, mtiles), 256, SMEM_GEMM>>>(feat, pWt, pH, N_NODES, 512);
    aggregate_kernel<512, true><<<N_NODES, 128>>>(pH, b0, pX);

    // layer 1: hidden(512) -> hidden(512), ReLU
    transpose_kernel<<<dim3(512 / 32, 512 / 32), dim3(32, 8)>>>(W1, pWt, 512);
    gemm_tf32_mma<<<dim3(4, mtiles), 256, SMEM_GEMM>>>(pX, pWt, pH, N_NODES, 512);
    aggregate_kernel<512, true><<<N_NODES, 128>>>(pH, b1, pX);

    // layer 2: hidden(512) -> out(256), no activation
    transpose_kernel<<<dim3(256 / 32, 512 / 32), dim3(32, 8)>>>(W2, pWt, 256);
    gemm_tf32_mma<<<dim3(2, mtiles), 256, SMEM_GEMM>>>(pX, pWt, pH, N_NODES, 256);
    aggregate_kernel<256, false><<<N_NODES, 64>>>(pH, b2, out);
}

// round 4
// speedup vs baseline: 2.5152x; 1.0257x over previous
#include <cuda_runtime.h>
#include <cuda_bf16.h>
#include <cstdint>

#define N_NODES 50000
#define N_EDGES 800000
#define F_DIM   512
#define F_OUT   256

// ---------------- persistent device scratch (no allocs allowed) ----------------
__device__ float g_H[(size_t)N_NODES * F_DIM];   // GEMM output (pre-aggregation)
__device__ float g_X[(size_t)N_NODES * F_DIM];   // layer activation (tf32-rounded)
__device__ float g_Wt0[512 * 512];               // transposed+rounded weights: Wt[n][k]
__device__ float g_Wt1[512 * 512];
__device__ float g_Wt2[512 * 256 * 2];           // (padded, only 256*512 used)
__device__ int   g_cnt_out[N_NODES];
__device__ int   g_cnt_in[N_NODES];
__device__ float g_out_norm[N_NODES];
__device__ float g_in_norm[N_NODES];
__device__ int   g_row_ptr[N_NODES + 1];
__device__ int   g_cursor[N_NODES];
__device__ int   g_esrc[N_EDGES];
__device__ int   g_is64;

__device__ __forceinline__ float rna_tf32(float x) {
    float r;
    asm("cvt.rna.tf32.f32 %0, %1;" : "=f"(r) : "f"(x));
    return r;
}

// ============================ index dtype sniffing ============================
__global__ void detect_kernel(const int* p) {
    int all0 = 1;
    for (int i = 1; i < 256; i += 2)
        if (p[i] != 0) { all0 = 0; break; }
    g_is64 = all0;
}
__device__ __forceinline__ int load_idx(const void* p, int i) {
    if (g_is64) return (int)((const long long*)p)[i];
    return ((const int*)p)[i];
}

// ============================ graph preprocessing ============================
__global__ void zero_counts_kernel() {
    int i = blockIdx.x * blockDim.x + threadIdx.x;
    if (i < N_NODES) { g_cnt_out[i] = 0; g_cnt_in[i] = 0; }
}
__global__ void degree_kernel(const void* src, const void* dst) {
    int stride = gridDim.x * blockDim.x;
    for (int e = blockIdx.x * blockDim.x + threadIdx.x; e < N_EDGES; e += stride) {
        atomicAdd(&g_cnt_out[load_idx(src, e)], 1);
        atomicAdd(&g_cnt_in[load_idx(dst, e)], 1);
    }
}
__global__ void norm_kernel() {
    int i = blockIdx.x * blockDim.x + threadIdx.x;
    if (i < N_NODES) {
        int co = g_cnt_out[i]; if (co < 1) co = 1;
        int ci = g_cnt_in[i];  if (ci < 1) ci = 1;
        g_out_norm[i] = rsqrtf((float)co);
        g_in_norm[i]  = rsqrtf((float)ci);
    }
}
__global__ void scan_kernel() {
    __shared__ int sh[1024];
    __shared__ int carry;
    int tid = threadIdx.x;
    if (tid == 0) carry = 0;
    __syncthreads();
    for (int base = 0; base < N_NODES; base += 1024) {
        int i = base + tid;
        int v = (i < N_NODES) ? g_cnt_in[i] : 0;
        sh[tid] = v;
        __syncthreads();
        int mycarry = carry;
        for (int off = 1; off < 1024; off <<= 1) {
            int t = (tid >= off) ? sh[tid - off] : 0;
            __syncthreads();
            sh[tid] += t;
            __syncthreads();
        }
        int excl = mycarry + sh[tid] - v;
        if (i < N_NODES) { g_row_ptr[i] = excl; g_cursor[i] = excl; }
        int total = sh[1023];
        __syncthreads();
        if (tid == 0) carry = mycarry + total;
        __syncthreads();
    }
    if (tid == 0) g_row_ptr[N_NODES] = carry;
}
__global__ void fill_kernel(const void* src, const void* dst) {
    int stride = gridDim.x * blockDim.x;
    for (int e = blockIdx.x * blockDim.x + threadIdx.x; e < N_EDGES; e += stride) {
        int d = load_idx(dst, e);
        int pos = atomicAdd(&g_cursor[d], 1);
        g_esrc[pos] = load_idx(src, e);
    }
}

// ============================ tf32-rounding feature copy ============================
__global__ void cvt_feat_kernel(const float* __restrict__ in, float* __restrict__ out) {
    int i = blockIdx.x * blockDim.x + threadIdx.x;
    const size_t total = (size_t)N_NODES * F_DIM / 4;
    size_t stride = (size_t)gridDim.x * blockDim.x;
    for (size_t j = i; j < total; j += stride) {
        float4 v = reinterpret_cast<const float4*>(in)[j];
        v.x = rna_tf32(v.x); v.y = rna_tf32(v.y);
        v.z = rna_tf32(v.z); v.w = rna_tf32(v.w);
        reinterpret_cast<float4*>(out)[j] = v;
    }
}

// ============================ weight transpose (+ tf32 rounding) ============================
// Wt[n*512 + k] = rna(W[k*N + n])   (K always 512; N = 512 or 256)
__global__ void transpose_kernel(const float* __restrict__ W, float* __restrict__ Wt, int N) {
    __shared__ float tile[32][33];
    int n = blockIdx.x * 32 + threadIdx.x;
    int k = blockIdx.y * 32 + threadIdx.y;
    #pragma unroll
    for (int dy = 0; dy < 32; dy += 8)
        tile[threadIdx.y + dy][threadIdx.x] = W[(size_t)(k + dy) * N + n];
    __syncthreads();
    int n2 = blockIdx.x * 32 + threadIdx.y;
    int k2 = blockIdx.y * 32 + threadIdx.x;
    #pragma unroll
    for (int dy = 0; dy < 32; dy += 8)
        Wt[(size_t)(n2 + dy) * 512 + k2] = rna_tf32(tile[threadIdx.x][threadIdx.y + dy]);
}

// ============================ tf32 mma.sync GEMM ============================
// H[m, n] = (sum_k X[m,k] * Wt[n,k]) * out_norm[m]   — X, Wt already tf32-rounded.
// BM=128, BN=128, BK=32, 256 thr (8 warps), warp tile 64x32, double-buffer cp.async.
#define BK        32
#define ROW_STR   36
#define A_FLOATS  (128 * ROW_STR)
#define STAGE_FLOATS (2 * A_FLOATS)
#define SMEM_GEMM (2 * STAGE_FLOATS * 4)     // 73728 B

__device__ __forceinline__ uint32_t smem_u32(const void* p) {
    uint32_t a;
    asm("{ .reg .u64 t; cvta.to.shared.u64 t, %1; cvt.u32.u64 %0, t; }" : "=r"(a) : "l"(p));
    return a;
}
__device__ __forceinline__ void cp_async16(uint32_t dst, const void* src) {
    asm volatile("cp.async.ca.shared.global [%0], [%1], 16;" :: "r"(dst), "l"(src));
}
__device__ __forceinline__ void mma_tf32(float c[4],
                                         uint32_t a0, uint32_t a1, uint32_t a2, uint32_t a3,
                                         uint32_t b0, uint32_t b1) {
    asm volatile("mma.sync.aligned.m16n8k8.row.col.f32.tf32.tf32.f32 "
        "{%0,%1,%2,%3}, {%4,%5,%6,%7}, {%8,%9}, {%0,%1,%2,%3};"
        : "+f"(c[0]), "+f"(c[1]), "+f"(c[2]), "+f"(c[3])
        : "r"(a0), "r"(a1), "r"(a2), "r"(a3), "r"(b0), "r"(b1));
}

__global__ __launch_bounds__(256)
void gemm_tf32_mma(const float* __restrict__ X, const float* __restrict__ Wt,
                   float* __restrict__ H, int M, int N) {
    extern __shared__ float smem[];
    int tid  = threadIdx.x;
    int wid  = tid >> 5;
    int lane = tid & 31;
    int m0 = blockIdx.y * 128;
    int n0 = blockIdx.x * 128;

    int wm = wid & 1;
    int wn = wid >> 1;
    int qrow = lane >> 2;
    int qk   = lane & 3;

    int cr = tid >> 3;
    int cc = tid & 7;

    float acc[4][4][4];
    #pragma unroll
    for (int i = 0; i < 4; i++)
        #pragma unroll
        for (int j = 0; j < 4; j++)
            #pragma unroll
            for (int q = 0; q < 4; q++) acc[i][j][q] = 0.f;

    const int n_chunks = 512 / BK;

    {
        float* As = smem;
        float* Bs = smem + A_FLOATS;
        #pragma unroll
        for (int pass = 0; pass < 4; pass++) {
            int r = cr + pass * 32;
            uint32_t adst = smem_u32(&As[r * ROW_STR + cc * 4]);
            int grow = m0 + r;
            if (grow < M) cp_async16(adst, &X[(size_t)grow * 512 + cc * 4]);
            else *reinterpret_cast<float4*>(&As[r * ROW_STR + cc * 4]) = make_float4(0,0,0,0);
            uint32_t bdst = smem_u32(&Bs[r * ROW_STR + cc * 4]);
            cp_async16(bdst, &Wt[(size_t)(n0 + r) * 512 + cc * 4]);
        }
        asm volatile("cp.async.commit_group;");
    }

    for (int i = 0; i < n_chunks; i++) {
        if (i + 1 < n_chunks) {
            int k0 = (i + 1) * BK;
            float* As = smem + ((i + 1) & 1) * STAGE_FLOATS;
            float* Bs = As + A_FLOATS;
            #pragma unroll
            for (int pass = 0; pass < 4; pass++) {
                int r = cr + pass * 32;
                uint32_t adst = smem_u32(&As[r * ROW_STR + cc * 4]);
                int grow = m0 + r;
                if (grow < M) cp_async16(adst, &X[(size_t)grow * 512 + k0 + cc * 4]);
                else *reinterpret_cast<float4*>(&As[r * ROW_STR + cc * 4]) = make_float4(0,0,0,0);
                uint32_t bdst = smem_u32(&Bs[r * ROW_STR + cc * 4]);
                cp_async16(bdst, &Wt[(size_t)(n0 + r) * 512 + k0 + cc * 4]);
            }
            asm volatile("cp.async.commit_group;");
            asm volatile("cp.async.wait_group 1;");
        } else {
            asm volatile("cp.async.wait_group 0;");
        }
        __syncthreads();

        const uint32_t* As = reinterpret_cast<const uint32_t*>(smem + (i & 1) * STAGE_FLOATS);
        const uint32_t* Bs = As + A_FLOATS;

        #pragma unroll
        for (int kb = 0; kb < BK; kb += 8) {
            uint32_t af[4][4];
            #pragma unroll
            for (int mf = 0; mf < 4; mf++) {
                const uint32_t* ap = &As[(wm * 64 + mf * 16 + qrow) * ROW_STR + kb + qk];
                af[mf][0] = ap[0];
                af[mf][1] = ap[8 * ROW_STR];
                af[mf][2] = ap[4];
                af[mf][3] = ap[8 * ROW_STR + 4];
            }
            uint32_t bf[4][2];
            #pragma unroll
            for (int nf = 0; nf < 4; nf++) {
                const uint32_t* bp = &Bs[(wn * 32 + nf * 8 + qrow) * ROW_STR + kb + qk];
                bf[nf][0] = bp[0];
                bf[nf][1] = bp[4];
            }
            #pragma unroll
            for (int mf = 0; mf < 4; mf++)
                #pragma unroll
                for (int nf = 0; nf < 4; nf++)
                    mma_tf32(acc[mf][nf], af[mf][0], af[mf][1], af[mf][2], af[mf][3],
                             bf[nf][0], bf[nf][1]);
        }
        __syncthreads();
    }

    #pragma unroll
    for (int mf = 0; mf < 4; mf++) {
        int row  = m0 + wm * 64 + mf * 16 + qrow;
        int row8 = row + 8;
        float s0 = (row  < M) ? g_out_norm[row]  : 0.f;
        float s1 = (row8 < M) ? g_out_norm[row8] : 0.f;
        #pragma unroll
        for (int nf = 0; nf < 4; nf++) {
            int col = n0 + wn * 32 + nf * 8 + qk * 2;
            if (row < M) {
                float2 v = make_float2(acc[mf][nf][0] * s0, acc[mf][nf][1] * s0);
                *reinterpret_cast<float2*>(&H[(size_t)row * N + col]) = v;
            }
            if (row8 < M) {
                float2 v = make_float2(acc[mf][nf][2] * s1, acc[mf][nf][3] * s1);
                *reinterpret_cast<float2*>(&H[(size_t)row8 * N + col]) = v;
            }
        }
    }
}

// ============================ CSR gather-aggregate ============================
// ROUND_OUT: tf32-round the stored activation (for layers feeding another GEMM).
template <int WIDTH, bool RELU, bool ROUND_OUT>
__global__ void aggregate_kernel(const float* __restrict__ H,
                                 const float* __restrict__ bias,
                                 float* __restrict__ out) {
    int n = blockIdx.x;
    int c = threadIdx.x * 4;
    float4 acc = make_float4(0.f, 0.f, 0.f, 0.f);
    int e0 = g_row_ptr[n];
    int e1 = g_row_ptr[n + 1];
    for (int e = e0; e < e1; e++) {
        int s = g_esrc[e];
        float4 v = *reinterpret_cast<const float4*>(&H[(size_t)s * WIDTH + c]);
        acc.x += v.x; acc.y += v.y; acc.z += v.z; acc.w += v.w;
    }
    float inn = g_in_norm[n];
    float4 b = *reinterpret_cast<const float4*>(&bias[c]);
    float4 r;
    r.x = acc.x * inn + b.x;
    r.y = acc.y * inn + b.y;
    r.z = acc.z * inn + b.z;
    r.w = acc.w * inn + b.w;
    if (RELU) {
        r.x = fmaxf(r.x, 0.f); r.y = fmaxf(r.y, 0.f);
        r.z = fmaxf(r.z, 0.f); r.w = fmaxf(r.w, 0.f);
    }
    if (ROUND_OUT) {
        r.x = rna_tf32(r.x); r.y = rna_tf32(r.y);
        r.z = rna_tf32(r.z); r.w = rna_tf32(r.w);
    }
    *reinterpret_cast<float4*>(&out[(size_t)n * WIDTH + c]) = r;
}

// ============================ launch ============================
extern "C" void kernel_launch(void* const* d_in, const int* in_sizes, int n_in,
                              void* d_out, int out_size) {
    const float* feat = (const float*)d_in[0];
    const void*  src  = d_in[1];
    const void*  dst  = d_in[2];
    const float* W0   = (const float*)d_in[3];
    const float* b0   = (const float*)d_in[4];
    const float* W1   = (const float*)d_in[5];
    const float* b1   = (const float*)d_in[6];
    const float* W2   = (const float*)d_in[7];
    const float* b2   = (const float*)d_in[8];
    float* out = (float*)d_out;

    float *pH, *pX, *pWt0, *pWt1, *pWt2;
    cudaGetSymbolAddress((void**)&pH, g_H);
    cudaGetSymbolAddress((void**)&pX, g_X);
    cudaGetSymbolAddress((void**)&pWt0, g_Wt0);
    cudaGetSymbolAddress((void**)&pWt1, g_Wt1);
    cudaGetSymbolAddress((void**)&pWt2, g_Wt2);

    cudaFuncSetAttribute(gemm_tf32_mma, cudaFuncAttributeMaxDynamicSharedMemorySize, SMEM_GEMM);

    static cudaStream_t s2 = nullptr;
    static cudaEvent_t evFork = nullptr, evJoin = nullptr;
    if (!s2) {
        cudaStreamCreateWithFlags(&s2, cudaStreamNonBlocking);
        cudaEventCreateWithFlags(&evFork, cudaEventDisableTiming);
        cudaEventCreateWithFlags(&evJoin, cudaEventDisableTiming);
    }

    // ---- fork: graph preprocessing + W1/W2 transposes on side stream ----
    cudaEventRecord(evFork, 0);
    cudaStreamWaitEvent(s2, evFork, 0);

    detect_kernel<<<1, 1, 0, s2>>>((const int*)src);
    zero_counts_kernel<<<(N_NODES + 255) / 256, 256, 0, s2>>>();
    degree_kernel<<<512, 256, 0, s2>>>(src, dst);
    norm_kernel<<<(N_NODES + 255) / 256, 256, 0, s2>>>();
    scan_kernel<<<1, 1024, 0, s2>>>();
    fill_kernel<<<512, 256, 0, s2>>>(src, dst);
    transpose_kernel<<<dim3(512 / 32, 512 / 32), dim3(32, 8), 0, s2>>>(W1, pWt1, 512);
    transpose_kernel<<<dim3(256 / 32, 512 / 32), dim3(32, 8), 0, s2>>>(W2, pWt2, 256);
    cudaEventRecord(evJoin, s2);

    // ---- main stream: feature rounding + W0 transpose + GEMM0 (needs out_norm!) ----
    // NOTE: gemm reads g_out_norm, produced on s2 -> GEMM0 must wait for join.
    cvt_feat_kernel<<<1024, 256>>>(feat, pX);
    transpose_kernel<<<dim3(512 / 32, 512 / 32), dim3(32, 8)>>>(W0, pWt0, 512);

    cudaStreamWaitEvent(0, evJoin, 0);

    int mtiles = (N_NODES + 127) / 128;   // 391

    // layer 0: X(=rounded feat, 512) -> hidden(512), ReLU
    gemm_tf32_mma<<<dim3(4, mtiles), 256, SMEM_GEMM>>>(pX, pWt0, pH, N_NODES, 512);
    aggregate_kernel<512, true, true><<<N_NODES, 128>>>(pH, b0, pX);

    // layer 1
    gemm_tf32_mma<<<dim3(4, mtiles), 256, SMEM_GEMM>>>(pX, pWt1, pH, N_NODES, 512);
    aggregate_kernel<512, true, true><<<N_NODES, 128>>>(pH, b1, pX);

    // layer 2: hidden(512) -> out(256), no activation, full-precision store
    gemm_tf32_mma<<<dim3(2, mtiles), 256, SMEM_GEMM>>>(pX, pWt2, pH, N_NODES, 256);
    aggregate_kernel<256, false, false><<<N_NODES, 64>>>(pH, b2, out);
}

// round 5
// speedup vs baseline: 2.5155x; 1.0001x over previous
#include <cuda_runtime.h>
#include <cuda_bf16.h>
#include <cstdint>

#define N_NODES 50000
#define N_EDGES 800000
#define F_DIM   512
#define F_OUT   256

// ---------------- persistent device scratch (no allocs allowed) ----------------
__device__ float g_H[(size_t)N_NODES * F_DIM];   // GEMM output (pre-aggregation)
__device__ float g_X[(size_t)N_NODES * F_DIM];   // layer activation (tf32-rounded)
__device__ float g_Wt0[512 * 512];               // transposed+rounded weights: Wt[n][k]
__device__ float g_Wt1[512 * 512];
__device__ float g_Wt2[512 * 256 * 2];           // (padded, only 256*512 used)
__device__ int   g_cnt_out[N_NODES];
__device__ int   g_cnt_in[N_NODES];
__device__ float g_out_norm[N_NODES];
__device__ float g_in_norm[N_NODES];
__device__ int   g_row_ptr[N_NODES + 1];
__device__ int   g_cursor[N_NODES];
__device__ int   g_esrc[N_EDGES];
__device__ int   g_is64;

__device__ __forceinline__ float rna_tf32(float x) {
    float r;
    asm("cvt.rna.tf32.f32 %0, %1;" : "=f"(r) : "f"(x));
    return r;
}

// ============================ index dtype sniffing ============================
__global__ void detect_kernel(const int* p) {
    int all0 = 1;
    for (int i = 1; i < 256; i += 2)
        if (p[i] != 0) { all0 = 0; break; }
    g_is64 = all0;
}
__device__ __forceinline__ int load_idx(const void* p, int i) {
    if (g_is64) return (int)((const long long*)p)[i];
    return ((const int*)p)[i];
}

// ============================ graph preprocessing ============================
__global__ void zero_counts_kernel() {
    int i = blockIdx.x * blockDim.x + threadIdx.x;
    if (i < N_NODES) { g_cnt_out[i] = 0; g_cnt_in[i] = 0; }
}
__global__ void degree_kernel(const void* src, const void* dst) {
    int stride = gridDim.x * blockDim.x;
    for (int e = blockIdx.x * blockDim.x + threadIdx.x; e < N_EDGES; e += stride) {
        atomicAdd(&g_cnt_out[load_idx(src, e)], 1);
        atomicAdd(&g_cnt_in[load_idx(dst, e)], 1);
    }
}
__global__ void norm_kernel() {
    int i = blockIdx.x * blockDim.x + threadIdx.x;
    if (i < N_NODES) {
        int co = g_cnt_out[i]; if (co < 1) co = 1;
        int ci = g_cnt_in[i];  if (ci < 1) ci = 1;
        g_out_norm[i] = rsqrtf((float)co);
        g_in_norm[i]  = rsqrtf((float)ci);
    }
}
__global__ void scan_kernel() {
    __shared__ int sh[1024];
    __shared__ int carry;
    int tid = threadIdx.x;
    if (tid == 0) carry = 0;
    __syncthreads();
    for (int base = 0; base < N_NODES; base += 1024) {
        int i = base + tid;
        int v = (i < N_NODES) ? g_cnt_in[i] : 0;
        sh[tid] = v;
        __syncthreads();
        int mycarry = carry;
        for (int off = 1; off < 1024; off <<= 1) {
            int t = (tid >= off) ? sh[tid - off] : 0;
            __syncthreads();
            sh[tid] += t;
            __syncthreads();
        }
        int excl = mycarry + sh[tid] - v;
        if (i < N_NODES) { g_row_ptr[i] = excl; g_cursor[i] = excl; }
        int total = sh[1023];
        __syncthreads();
        if (tid == 0) carry = mycarry + total;
        __syncthreads();
    }
    if (tid == 0) g_row_ptr[N_NODES] = carry;
}
__global__ void fill_kernel(const void* src, const void* dst) {
    int stride = gridDim.x * blockDim.x;
    for (int e = blockIdx.x * blockDim.x + threadIdx.x; e < N_EDGES; e += stride) {
        int d = load_idx(dst, e);
        int pos = atomicAdd(&g_cursor[d], 1);
        g_esrc[pos] = load_idx(src, e);
    }
}

// ============================ tf32-rounding feature copy ============================
__global__ void cvt_feat_kernel(const float* __restrict__ in, float* __restrict__ out) {
    int i = blockIdx.x * blockDim.x + threadIdx.x;
    const size_t total = (size_t)N_NODES * F_DIM / 4;
    size_t stride = (size_t)gridDim.x * blockDim.x;
    for (size_t j = i; j < total; j += stride) {
        float4 v = reinterpret_cast<const float4*>(in)[j];
        v.x = rna_tf32(v.x); v.y = rna_tf32(v.y);
        v.z = rna_tf32(v.z); v.w = rna_tf32(v.w);
        reinterpret_cast<float4*>(out)[j] = v;
    }
}

// ============================ weight transpose (+ tf32 rounding) ============================
// Wt[n*512 + k] = rna(W[k*N + n])   (K always 512; N = 512 or 256)
__global__ void transpose_kernel(const float* __restrict__ W, float* __restrict__ Wt, int N) {
    __shared__ float tile[32][33];
    int n = blockIdx.x * 32 + threadIdx.x;
    int k = blockIdx.y * 32 + threadIdx.y;
    #pragma unroll
    for (int dy = 0; dy < 32; dy += 8)
        tile[threadIdx.y + dy][threadIdx.x] = W[(size_t)(k + dy) * N + n];
    __syncthreads();
    int n2 = blockIdx.x * 32 + threadIdx.y;
    int k2 = blockIdx.y * 32 + threadIdx.x;
    #pragma unroll
    for (int dy = 0; dy < 32; dy += 8)
        Wt[(size_t)(n2 + dy) * 512 + k2] = rna_tf32(tile[threadIdx.x][threadIdx.y + dy]);
}

// ============================ tf32 mma.sync GEMM ============================
// H[m, n] = (sum_k X[m,k] * Wt[n,k]) * out_norm[m]   — X, Wt already tf32-rounded.
// BM=128, BN=128, BK=32, 256 thr (8 warps), warp tile 64x32, double-buffer cp.async.
#define BK        32
#define ROW_STR   36
#define A_FLOATS  (128 * ROW_STR)
#define STAGE_FLOATS (2 * A_FLOATS)
#define SMEM_GEMM (2 * STAGE_FLOATS * 4)     // 73728 B

__device__ __forceinline__ uint32_t smem_u32(const void* p) {
    uint32_t a;
    asm("{ .reg .u64 t; cvta.to.shared.u64 t, %1; cvt.u32.u64 %0, t; }" : "=r"(a) : "l"(p));
    return a;
}
__device__ __forceinline__ void cp_async16(uint32_t dst, const void* src) {
    asm volatile("cp.async.ca.shared.global [%0], [%1], 16;" :: "r"(dst), "l"(src));
}
__device__ __forceinline__ void mma_tf32(float c[4],
                                         uint32_t a0, uint32_t a1, uint32_t a2, uint32_t a3,
                                         uint32_t b0, uint32_t b1) {
    asm volatile("mma.sync.aligned.m16n8k8.row.col.f32.tf32.tf32.f32 "
        "{%0,%1,%2,%3}, {%4,%5,%6,%7}, {%8,%9}, {%0,%1,%2,%3};"
        : "+f"(c[0]), "+f"(c[1]), "+f"(c[2]), "+f"(c[3])
        : "r"(a0), "r"(a1), "r"(a2), "r"(a3), "r"(b0), "r"(b1));
}

__global__ __launch_bounds__(256)
void gemm_tf32_mma(const float* __restrict__ X, const float* __restrict__ Wt,
                   float* __restrict__ H, int M, int N) {
    extern __shared__ float smem[];
    int tid  = threadIdx.x;
    int wid  = tid >> 5;
    int lane = tid & 31;
    int m0 = blockIdx.y * 128;
    int n0 = blockIdx.x * 128;

    int wm = wid & 1;
    int wn = wid >> 1;
    int qrow = lane >> 2;
    int qk   = lane & 3;

    int cr = tid >> 3;
    int cc = tid & 7;

    float acc[4][4][4];
    #pragma unroll
    for (int i = 0; i < 4; i++)
        #pragma unroll
        for (int j = 0; j < 4; j++)
            #pragma unroll
            for (int q = 0; q < 4; q++) acc[i][j][q] = 0.f;

    const int n_chunks = 512 / BK;

    {
        float* As = smem;
        float* Bs = smem + A_FLOATS;
        #pragma unroll
        for (int pass = 0; pass < 4; pass++) {
            int r = cr + pass * 32;
            uint32_t adst = smem_u32(&As[r * ROW_STR + cc * 4]);
            int grow = m0 + r;
            if (grow < M) cp_async16(adst, &X[(size_t)grow * 512 + cc * 4]);
            else *reinterpret_cast<float4*>(&As[r * ROW_STR + cc * 4]) = make_float4(0,0,0,0);
            uint32_t bdst = smem_u32(&Bs[r * ROW_STR + cc * 4]);
            cp_async16(bdst, &Wt[(size_t)(n0 + r) * 512 + cc * 4]);
        }
        asm volatile("cp.async.commit_group;");
    }

    for (int i = 0; i < n_chunks; i++) {
        if (i + 1 < n_chunks) {
            int k0 = (i + 1) * BK;
            float* As = smem + ((i + 1) & 1) * STAGE_FLOATS;
            float* Bs = As + A_FLOATS;
            #pragma unroll
            for (int pass = 0; pass < 4; pass++) {
                int r = cr + pass * 32;
                uint32_t adst = smem_u32(&As[r * ROW_STR + cc * 4]);
                int grow = m0 + r;
                if (grow < M) cp_async16(adst, &X[(size_t)grow * 512 + k0 + cc * 4]);
                else *reinterpret_cast<float4*>(&As[r * ROW_STR + cc * 4]) = make_float4(0,0,0,0);
                uint32_t bdst = smem_u32(&Bs[r * ROW_STR + cc * 4]);
                cp_async16(bdst, &Wt[(size_t)(n0 + r) * 512 + k0 + cc * 4]);
            }
            asm volatile("cp.async.commit_group;");
            asm volatile("cp.async.wait_group 1;");
        } else {
            asm volatile("cp.async.wait_group 0;");
        }
        __syncthreads();

        const uint32_t* As = reinterpret_cast<const uint32_t*>(smem + (i & 1) * STAGE_FLOATS);
        const uint32_t* Bs = As + A_FLOATS;

        #pragma unroll
        for (int kb = 0; kb < BK; kb += 8) {
            uint32_t af[4][4];
            #pragma unroll
            for (int mf = 0; mf < 4; mf++) {
                const uint32_t* ap = &As[(wm * 64 + mf * 16 + qrow) * ROW_STR + kb + qk];
                af[mf][0] = ap[0];
                af[mf][1] = ap[8 * ROW_STR];
                af[mf][2] = ap[4];
                af[mf][3] = ap[8 * ROW_STR + 4];
            }
            uint32_t bf[4][2];
            #pragma unroll
            for (int nf = 0; nf < 4; nf++) {
                const uint32_t* bp = &Bs[(wn * 32 + nf * 8 + qrow) * ROW_STR + kb + qk];
                bf[nf][0] = bp[0];
                bf[nf][1] = bp[4];
            }
            #pragma unroll
            for (int mf = 0; mf < 4; mf++)
                #pragma unroll
                for (int nf = 0; nf < 4; nf++)
                    mma_tf32(acc[mf][nf], af[mf][0], af[mf][1], af[mf][2], af[mf][3],
                             bf[nf][0], bf[nf][1]);
        }
        __syncthreads();
    }

    #pragma unroll
    for (int mf = 0; mf < 4; mf++) {
        int row  = m0 + wm * 64 + mf * 16 + qrow;
        int row8 = row + 8;
        float s0 = (row  < M) ? g_out_norm[row]  : 0.f;
        float s1 = (row8 < M) ? g_out_norm[row8] : 0.f;
        #pragma unroll
        for (int nf = 0; nf < 4; nf++) {
            int col = n0 + wn * 32 + nf * 8 + qk * 2;
            if (row < M) {
                float2 v = make_float2(acc[mf][nf][0] * s0, acc[mf][nf][1] * s0);
                *reinterpret_cast<float2*>(&H[(size_t)row * N + col]) = v;
            }
            if (row8 < M) {
                float2 v = make_float2(acc[mf][nf][2] * s1, acc[mf][nf][3] * s1);
                *reinterpret_cast<float2*>(&H[(size_t)row8 * N + col]) = v;
            }
        }
    }
}

// ============================ CSR gather-aggregate ============================
// ROUND_OUT: tf32-round the stored activation (for layers feeding another GEMM).
template <int WIDTH, bool RELU, bool ROUND_OUT>
__global__ void aggregate_kernel(const float* __restrict__ H,
                                 const float* __restrict__ bias,
                                 float* __restrict__ out) {
    int n = blockIdx.x;
    int c = threadIdx.x * 4;
    float4 acc = make_float4(0.f, 0.f, 0.f, 0.f);
    int e0 = g_row_ptr[n];
    int e1 = g_row_ptr[n + 1];
    for (int e = e0; e < e1; e++) {
        int s = g_esrc[e];
        float4 v = *reinterpret_cast<const float4*>(&H[(size_t)s * WIDTH + c]);
        acc.x += v.x; acc.y += v.y; acc.z += v.z; acc.w += v.w;
    }
    float inn = g_in_norm[n];
    float4 b = *reinterpret_cast<const float4*>(&bias[c]);
    float4 r;
    r.x = acc.x * inn + b.x;
    r.y = acc.y * inn + b.y;
    r.z = acc.z * inn + b.z;
    r.w = acc.w * inn + b.w;
    if (RELU) {
        r.x = fmaxf(r.x, 0.f); r.y = fmaxf(r.y, 0.f);
        r.z = fmaxf(r.z, 0.f); r.w = fmaxf(r.w, 0.f);
    }
    if (ROUND_OUT) {
        r.x = rna_tf32(r.x); r.y = rna_tf32(r.y);
        r.z = rna_tf32(r.z); r.w = rna_tf32(r.w);
    }
    *reinterpret_cast<float4*>(&out[(size_t)n * WIDTH + c]) = r;
}

// ============================ launch ============================
extern "C" void kernel_launch(void* const* d_in, const int* in_sizes, int n_in,
                              void* d_out, int out_size) {
    const float* feat = (const float*)d_in[0];
    const void*  src  = d_in[1];
    const void*  dst  = d_in[2];
    const float* W0   = (const float*)d_in[3];
    const float* b0   = (const float*)d_in[4];
    const float* W1   = (const float*)d_in[5];
    const float* b1   = (const float*)d_in[6];
    const float* W2   = (const float*)d_in[7];
    const float* b2   = (const float*)d_in[8];
    float* out = (float*)d_out;

    float *pH, *pX, *pWt0, *pWt1, *pWt2;
    cudaGetSymbolAddress((void**)&pH, g_H);
    cudaGetSymbolAddress((void**)&pX, g_X);
    cudaGetSymbolAddress((void**)&pWt0, g_Wt0);
    cudaGetSymbolAddress((void**)&pWt1, g_Wt1);
    cudaGetSymbolAddress((void**)&pWt2, g_Wt2);

    cudaFuncSetAttribute(gemm_tf32_mma, cudaFuncAttributeMaxDynamicSharedMemorySize, SMEM_GEMM);

    static cudaStream_t s2 = nullptr;
    static cudaEvent_t evFork = nullptr, evJoin = nullptr;
    if (!s2) {
        cudaStreamCreateWithFlags(&s2, cudaStreamNonBlocking);
        cudaEventCreateWithFlags(&evFork, cudaEventDisableTiming);
        cudaEventCreateWithFlags(&evJoin, cudaEventDisableTiming);
    }

    // ---- fork: graph preprocessing + W1/W2 transposes on side stream ----
    cudaEventRecord(evFork, 0);
    cudaStreamWaitEvent(s2, evFork, 0);

    detect_kernel<<<1, 1, 0, s2>>>((const int*)src);
    zero_counts_kernel<<<(N_NODES + 255) / 256, 256, 0, s2>>>();
    degree_kernel<<<512, 256, 0, s2>>>(src, dst);
    norm_kernel<<<(N_NODES + 255) / 256, 256, 0, s2>>>();
    scan_kernel<<<1, 1024, 0, s2>>>();
    fill_kernel<<<512, 256, 0, s2>>>(src, dst);
    transpose_kernel<<<dim3(512 / 32, 512 / 32), dim3(32, 8), 0, s2>>>(W1, pWt1, 512);
    transpose_kernel<<<dim3(256 / 32, 512 / 32), dim3(32, 8), 0, s2>>>(W2, pWt2, 256);
    cudaEventRecord(evJoin, s2);

    // ---- main stream: feature rounding + W0 transpose + GEMM0 (needs out_norm!) ----
    // NOTE: gemm reads g_out_norm, produced on s2 -> GEMM0 must wait for join.
    cvt_feat_kernel<<<1024, 256>>>(feat, pX);
    transpose_kernel<<<dim3(512 / 32, 512 / 32), dim3(32, 8)>>>(W0, pWt0, 512);

    cudaStreamWaitEvent(0, evJoin, 0);

    int mtiles = (N_NODES + 127) / 128;   // 391

    // layer 0: X(=rounded feat, 512) -> hidden(512), ReLU
    gemm_tf32_mma<<<dim3(4, mtiles), 256, SMEM_GEMM>>>(pX, pWt0, pH, N_NODES, 512);
    aggregate_kernel<512, true, true><<<N_NODES, 128>>>(pH, b0, pX);

    // layer 1
    gemm_tf32_mma<<<dim3(4, mtiles), 256, SMEM_GEMM>>>(pX, pWt1, pH, N_NODES, 512);
    aggregate_kernel<512, true, true><<<N_NODES, 128>>>(pH, b1, pX);

    // layer 2: hidden(512) -> out(256), no activation, full-precision store
    gemm_tf32_mma<<<dim3(2, mtiles), 256, SMEM_GEMM>>>(pX, pWt2, pH, N_NODES, 256);
    aggregate_kernel<256, false, false><<<N_NODES, 64>>>(pH, b2, out);
}